// round 2
// baseline (speedup 1.0000x reference)
#include <cuda_runtime.h>
#include <cuda_bf16.h>
#include <cstdint>

// Problem constants
constexpr int B_  = 16384;
constexpr int F_  = 26;
constexpr int V_  = 100000;
constexpr int D_  = 64;
constexpr int H1_ = 512;
constexpr int H2_ = 256;
constexpr int NPAIR = F_ * (F_ - 1) / 2;      // 325
constexpr int INP   = F_ * D_ + NPAIR;        // 1989
constexpr int KP    = 2048;                   // padded K for GEMM1

// Scratch (static device globals — no allocation in kernel_launch)
__device__ float g_joint[(size_t)B_ * KP];    // 134 MB
__device__ float g_W1p[(size_t)KP * H1_];     // 4 MB
__device__ float g_h1[(size_t)B_ * H1_];      // 33.5 MB
__device__ float g_h2[(size_t)B_ * H2_];      // 16.8 MB

// ---------------------------------------------------------------------------
// Kernel 1: pad W1 [1989,512] -> [2048,512] with zero rows
// ---------------------------------------------------------------------------
__global__ void pad_w1_kernel(const float* __restrict__ W1)
{
    int i = blockIdx.x * blockDim.x + threadIdx.x;
    if (i >= KP * H1_) return;
    g_W1p[i] = (i < INP * H1_) ? W1[i] : 0.0f;
}

// ---------------------------------------------------------------------------
// Kernel 2: per-sample gather + Gram upper-triangle -> joint row (K padded)
// One block (128 threads) per sample.
// ---------------------------------------------------------------------------
__global__ __launch_bounds__(128) void build_joint_kernel(
    const int*   __restrict__ idx,
    const float* __restrict__ tables)
{
    constexpr int SROW = 65;                  // smem row stride (bank-conflict-free)
    __shared__ float semb[F_ * SROW];
    __shared__ int   sidx[F_];

    const int b   = blockIdx.x;
    const int tid = threadIdx.x;

    if (tid < F_) sidx[tid] = idx[b * F_ + tid];
    __syncthreads();

    float* jrow = g_joint + (size_t)b * KP;

    // gather: 26 rows x 16 float4 = 416 float4 loads
    for (int t = tid; t < F_ * 16; t += 128) {
        const int f = t >> 4;
        const int q = t & 15;
        const float4 v = reinterpret_cast<const float4*>(tables)
                            [((size_t)f * V_ + sidx[f]) * 16 + q];
        reinterpret_cast<float4*>(jrow)[f * 16 + q] = v;   // flat emb part of joint
        float* s = &semb[f * SROW + q * 4];
        s[0] = v.x; s[1] = v.y; s[2] = v.z; s[3] = v.w;
    }
    __syncthreads();

    // Gram upper triangle in np.triu_indices(F, k=1) order
    for (int p = tid; p < NPAIR; p += 128) {
        int i = 0, rem = p, len = F_ - 1;
        while (rem >= len) { rem -= len; len--; i++; }
        const int j = i + 1 + rem;
        const float* a = &semb[i * SROW];
        const float* c = &semb[j * SROW];
        float acc = 0.0f;
#pragma unroll
        for (int k = 0; k < D_; k++) acc = fmaf(a[k], c[k], acc);
        jrow[F_ * D_ + p] = acc;
    }

    // zero K padding
    for (int c = INP + tid; c < KP; c += 128) jrow[c] = 0.0f;
}

// ---------------------------------------------------------------------------
// Kernel 3: tiled fp32 SGEMM, C = relu?(A@B + bias)
// A: MxK row-major, B: KxN row-major, C: MxN row-major.
// 128x128 tile, BK=8, 256 threads, 8x8 per-thread register tile.
// Requires M%128==0, N%128==0, K%8==0.
// ---------------------------------------------------------------------------
template<bool RELU>
__global__ __launch_bounds__(256, 1) void sgemm128_kernel(
    int M, int N, int K,
    const float* __restrict__ A,
    const float* __restrict__ Bm,
    const float* __restrict__ bias,
    float*       __restrict__ C)
{
    constexpr int BM = 128, BN = 128, BK = 8, TM = 8, TN = 8;
    __shared__ float As[BK][BM];
    __shared__ float Bs[BK][BN];

    const int tid  = threadIdx.x;
    const int tx   = tid & 15;        // 0..15 -> column group
    const int ty   = tid >> 4;        // 0..15 -> row group
    const int row0 = blockIdx.y * BM;
    const int col0 = blockIdx.x * BN;

    // load mapping
    const int arow  = tid >> 1;       // 0..127
    const int acol4 = (tid & 1) * 4;  // 0 or 4
    const int brow  = tid >> 5;       // 0..7
    const int bcol4 = (tid & 31) * 4; // 0..124

    float acc[TM][TN];
#pragma unroll
    for (int i = 0; i < TM; i++)
#pragma unroll
        for (int j = 0; j < TN; j++) acc[i][j] = 0.0f;

    const float* Aptr = A + (size_t)(row0 + arow) * K + acol4;
    const float* Bptr = Bm + (size_t)brow * N + col0 + bcol4;

    for (int k0 = 0; k0 < K; k0 += BK) {
        const float4 av = *reinterpret_cast<const float4*>(Aptr + k0);
        As[acol4 + 0][arow] = av.x;
        As[acol4 + 1][arow] = av.y;
        As[acol4 + 2][arow] = av.z;
        As[acol4 + 3][arow] = av.w;
        *reinterpret_cast<float4*>(&Bs[brow][bcol4]) =
            *reinterpret_cast<const float4*>(Bptr + (size_t)k0 * N);
        __syncthreads();

#pragma unroll
        for (int k = 0; k < BK; k++) {
            float ar[TM], br[TN];
#pragma unroll
            for (int i = 0; i < TM; i++) ar[i] = As[k][ty * TM + i];
#pragma unroll
            for (int j = 0; j < TN; j++) br[j] = Bs[k][tx * TN + j];
#pragma unroll
            for (int i = 0; i < TM; i++)
#pragma unroll
                for (int j = 0; j < TN; j++)
                    acc[i][j] = fmaf(ar[i], br[j], acc[i][j]);
        }
        __syncthreads();
    }

    // epilogue: bias + optional relu, float4 stores
    float bv[TN];
#pragma unroll
    for (int j = 0; j < TN; j++) bv[j] = bias[col0 + tx * TN + j];

#pragma unroll
    for (int i = 0; i < TM; i++) {
        float* crow = C + (size_t)(row0 + ty * TM + i) * N + col0 + tx * TN;
        float4 v0, v1;
        float r[TN];
#pragma unroll
        for (int j = 0; j < TN; j++) {
            r[j] = acc[i][j] + bv[j];
            if (RELU) r[j] = fmaxf(r[j], 0.0f);
        }
        v0.x = r[0]; v0.y = r[1]; v0.z = r[2]; v0.w = r[3];
        v1.x = r[4]; v1.y = r[5]; v1.z = r[6]; v1.w = r[7];
        reinterpret_cast<float4*>(crow)[0] = v0;
        reinterpret_cast<float4*>(crow)[1] = v1;
    }
}

// ---------------------------------------------------------------------------
// Kernel 4: final GEMV  out[b] = dot(h2[b,:], W3) + b3  (one warp per row)
// ---------------------------------------------------------------------------
__global__ void gemv3_kernel(const float* __restrict__ W3,
                             const float* __restrict__ b3,
                             float*       __restrict__ out)
{
    const int gwarp = (blockIdx.x * blockDim.x + threadIdx.x) >> 5;
    const int lane  = threadIdx.x & 31;
    if (gwarp >= B_) return;
    const float* r = g_h2 + (size_t)gwarp * H2_;
    float acc = 0.0f;
#pragma unroll
    for (int k = lane; k < H2_; k += 32) acc = fmaf(r[k], W3[k], acc);
#pragma unroll
    for (int o = 16; o; o >>= 1) acc += __shfl_xor_sync(0xFFFFFFFFu, acc, o);
    if (lane == 0) out[gwarp] = acc + b3[0];
}

// ---------------------------------------------------------------------------
// launch
// ---------------------------------------------------------------------------
extern "C" void kernel_launch(void* const* d_in, const int* in_sizes, int n_in,
                              void* d_out, int out_size)
{
    const int*   idx    = (const int*)  d_in[0];   // [B, F] int32
    const float* tables = (const float*)d_in[1];   // [F, V, D]
    const float* W1     = (const float*)d_in[2];   // [INP, H1]
    const float* b1     = (const float*)d_in[3];   // [H1]
    const float* W2     = (const float*)d_in[4];   // [H1, H2]
    const float* b2     = (const float*)d_in[5];   // [H2]
    const float* W3     = (const float*)d_in[6];   // [H2, 1]
    const float* b3     = (const float*)d_in[7];   // [1]
    float*       out    = (float*)d_out;

    // device symbol addresses (usable directly as kernel args via globals;
    // kernels reference the __device__ arrays by symbol)
    float* joint; cudaGetSymbolAddress((void**)&joint, g_joint);
    float* w1p;   cudaGetSymbolAddress((void**)&w1p,   g_W1p);
    float* h1;    cudaGetSymbolAddress((void**)&h1,    g_h1);
    float* h2;    cudaGetSymbolAddress((void**)&h2,    g_h2);

    // 1. pad W1
    pad_w1_kernel<<<(KP * H1_ + 255) / 256, 256>>>(W1);

    // 2. gather + interactions
    build_joint_kernel<<<B_, 128>>>(idx, tables);

    // 3. layer 1: [B, 2048] x [2048, 512] + b1, relu
    {
        dim3 grid(H1_ / 128, B_ / 128);
        sgemm128_kernel<true><<<grid, 256>>>(B_, H1_, KP, joint, w1p, b1, h1);
    }

    // 4. layer 2: [B, 512] x [512, 256] + b2, relu
    {
        dim3 grid(H2_ / 128, B_ / 128);
        sgemm128_kernel<true><<<grid, 256>>>(B_, H2_, H1_, h1, W2, b2, h2);
    }

    // 5. layer 3: [B, 256] x [256, 1] + b3
    gemv3_kernel<<<(B_ * 32 + 255) / 256, 256>>>(W3, b3, out);
}

// round 7
// speedup vs baseline: 2.0906x; 2.0906x over previous
#include <cuda_runtime.h>
#include <cuda_bf16.h>
#include <cstdint>

// ---------------------------------------------------------------------------
// Problem constants
// ---------------------------------------------------------------------------
constexpr int B_  = 16384;
constexpr int F_  = 26;
constexpr int V_  = 100000;
constexpr int D_  = 64;
constexpr int H1_ = 512;
constexpr int H2_ = 256;
constexpr int NPAIR = F_ * (F_ - 1) / 2;      // 325
constexpr int INP   = F_ * D_ + NPAIR;        // 1989
constexpr int K1    = 2048;                    // padded K, layer 1
constexpr int K2    = 512;                     // K, layer 2 (= H1)

// ---------------------------------------------------------------------------
// Scratch (__device__ globals; no allocation anywhere)
// ---------------------------------------------------------------------------
__device__ __nv_bfloat16 g_A  [(size_t)B_  * 2 * K1];   // joint split: [b][hi|lo]
__device__ __nv_bfloat16 g_W1t[(size_t)H1_ * 2 * K1];   // W1^T split:  [n][hi|lo]
__device__ __nv_bfloat16 g_W2t[(size_t)H2_ * 2 * K2];   // W2^T split
__device__ __nv_bfloat16 g_h1b[(size_t)B_  * 2 * K2];   // h1 split (input of layer 2)
__device__ float         g_h2 [(size_t)B_  * H2_];      // h2 fp32

__device__ __forceinline__ void split_bf16(float v, __nv_bfloat16& hi, __nv_bfloat16& lo) {
    hi = __float2bfloat16(v);
    lo = __float2bfloat16(v - __bfloat162float(hi));
}

__device__ __forceinline__ uint32_t smem_u32(const void* p) {
    uint32_t a;
    asm("{ .reg .u64 t; cvta.to.shared.u64 t, %1; cvt.u32.u64 %0, t; }"
        : "=r"(a) : "l"(p));
    return a;
}

// ldmatrix x4 (non-transposed), b16 8x8 tiles
__device__ __forceinline__ void ldsm_x4(uint32_t* r, uint32_t addr) {
    asm volatile("ldmatrix.sync.aligned.m8n8.x4.shared.b16 {%0,%1,%2,%3}, [%4];"
                 : "=r"(r[0]), "=r"(r[1]), "=r"(r[2]), "=r"(r[3]) : "r"(addr));
}

// mma m16n8k16 bf16 -> f32
__device__ __forceinline__ void mma16816(float* c, const uint32_t* a, const uint32_t* b) {
    asm volatile(
        "mma.sync.aligned.m16n8k16.row.col.f32.bf16.bf16.f32 "
        "{%0,%1,%2,%3}, {%4,%5,%6,%7}, {%8,%9}, {%0,%1,%2,%3};"
        : "+f"(c[0]), "+f"(c[1]), "+f"(c[2]), "+f"(c[3])
        : "r"(a[0]), "r"(a[1]), "r"(a[2]), "r"(a[3]), "r"(b[0]), "r"(b[1]));
}

// ---------------------------------------------------------------------------
// Prep: W1^T split  [512][2*2048] from W1 [1989][512] (zero pad K)
// ---------------------------------------------------------------------------
__global__ void prep_w1_kernel(const float* __restrict__ W1)
{
    int i = blockIdx.x * blockDim.x + threadIdx.x;
    if (i >= H1_ * K1) return;
    int n = i >> 11;            // 0..511
    int k = i & (K1 - 1);       // 0..2047
    float v = (k < INP) ? W1[(size_t)k * H1_ + n] : 0.0f;
    __nv_bfloat16 hi, lo; split_bf16(v, hi, lo);
    g_W1t[(size_t)n * 2 * K1 + k]      = hi;
    g_W1t[(size_t)n * 2 * K1 + K1 + k] = lo;
}

// Prep: W2^T split [256][2*512] from W2 [512][256]
__global__ void prep_w2_kernel(const float* __restrict__ W2)
{
    int i = blockIdx.x * blockDim.x + threadIdx.x;
    if (i >= H2_ * K2) return;
    int n = i >> 9;             // 0..255
    int k = i & (K2 - 1);       // 0..511
    float v = W2[(size_t)k * H2_ + n];
    __nv_bfloat16 hi, lo; split_bf16(v, hi, lo);
    g_W2t[(size_t)n * 2 * K2 + k]      = hi;
    g_W2t[(size_t)n * 2 * K2 + K2 + k] = lo;
}

// ---------------------------------------------------------------------------
// build_joint: gather + Gram upper triangle -> split-bf16 joint row
// ---------------------------------------------------------------------------
__global__ __launch_bounds__(128) void build_joint_kernel(
    const int*   __restrict__ idx,
    const float* __restrict__ tables)
{
    constexpr int SROW = 65;
    __shared__ float semb[F_ * SROW];
    __shared__ int   sidx[F_];

    const int b   = blockIdx.x;
    const int tid = threadIdx.x;

    if (tid < F_) sidx[tid] = idx[b * F_ + tid];
    __syncthreads();

    __nv_bfloat16* jhi = g_A + (size_t)b * 2 * K1;
    __nv_bfloat16* jlo = jhi + K1;

    for (int t = tid; t < F_ * 16; t += 128) {
        const int f = t >> 4;
        const int q = t & 15;
        const float4 v = reinterpret_cast<const float4*>(tables)
                            [((size_t)f * V_ + sidx[f]) * 16 + q];
        float* s = &semb[f * SROW + q * 4];
        s[0] = v.x; s[1] = v.y; s[2] = v.z; s[3] = v.w;

        __nv_bfloat16 h[4], l[4];
        split_bf16(v.x, h[0], l[0]); split_bf16(v.y, h[1], l[1]);
        split_bf16(v.z, h[2], l[2]); split_bf16(v.w, h[3], l[3]);
        const int c = f * 64 + q * 4;
        *reinterpret_cast<uint2*>(jhi + c) = *reinterpret_cast<uint2*>(h);
        *reinterpret_cast<uint2*>(jlo + c) = *reinterpret_cast<uint2*>(l);
    }
    __syncthreads();

    for (int p = tid; p < NPAIR; p += 128) {
        int i = 0, rem = p, len = F_ - 1;
        while (rem >= len) { rem -= len; len--; i++; }
        const int j = i + 1 + rem;
        const float* a = &semb[i * SROW];
        const float* c = &semb[j * SROW];
        float acc = 0.0f;
#pragma unroll
        for (int k = 0; k < D_; k++) acc = fmaf(a[k], c[k], acc);
        __nv_bfloat16 hi, lo; split_bf16(acc, hi, lo);
        jhi[F_ * D_ + p] = hi;
        jlo[F_ * D_ + p] = lo;
    }

    for (int c = INP + tid; c < K1; c += 128) {
        jhi[c] = __float2bfloat16(0.0f);
        jlo[c] = __float2bfloat16(0.0f);
    }
}

// ---------------------------------------------------------------------------
// mma.sync split-bf16 GEMM + bias + ReLU
//   A : [M][2*KSEG] bf16 (hi|lo)   M-major, K contiguous
//   Bw: [NT][2*KSEG] bf16 (hi|lo)  N-major, K contiguous (= B col-major)
//   C = relu(A @ B + bias) via hi*hi + lo*hi + hi*lo (3 K passes)
//   CTA 128x128, BK=64, 256 thr (8 warps 4Mx2N, warp tile 32x64).
//   Smem: XOR-swizzled 128B rows; double buffered (A0|B0|A1|B1 = 64 KB).
// ---------------------------------------------------------------------------
template<int NT, int KSEG, bool OUT_SPLIT>
__global__ __launch_bounds__(256) void gemm_mma_kernel(
    const __nv_bfloat16* __restrict__ A,
    const __nv_bfloat16* __restrict__ Bw,
    const float* __restrict__ bias,
    void* __restrict__ Cout)
{
    constexpr int ASTR  = 2 * KSEG;
    constexpr int BK    = 64;
    constexpr int TBYTES = 128 * 128;           // one tile buffer: 128 rows x 128 B
    constexpr int CPS   = KSEG / BK;
    constexpr int TOTAL = 3 * CPS;

    extern __shared__ char smem_raw[];
    const uint32_t sb = smem_u32(smem_raw);
    // buffers: A0 @0, B0 @TBYTES, A1 @2*TBYTES, B1 @3*TBYTES

    const int tid  = threadIdx.x;
    const int wid  = tid >> 5;
    const int lane = tid & 31;
    const int wm   = wid & 3;              // 0..3 (M groups of 32)
    const int wn   = wid >> 2;             // 0..1 (N groups of 64)
    const int row0 = blockIdx.y * 128;
    const int col0 = blockIdx.x * 128;

    // global staging coords: each thread owns 4 rows (stride 32), one 16B chunk
    const int lr = tid >> 3;               // 0..31
    const int lq = tid & 7;                // 0..7 (16B chunk within 128B row)

    // ldmatrix per-lane coords
    const int sub = lane >> 3;             // which 8x8 matrix
    const int r8  = lane & 7;              // row within 8x8

    float acc[2][8][4];
#pragma unroll
    for (int i = 0; i < 2; i++)
#pragma unroll
        for (int j = 0; j < 8; j++)
#pragma unroll
            for (int e = 0; e < 4; e++) acc[i][j][e] = 0.0f;

    uint4 ra[4], rb[4];

    // prefetch chunk 0 (seg 0: hi*hi)
#pragma unroll
    for (int it = 0; it < 4; it++) {
        const int r = lr + it * 32;
        ra[it] = *reinterpret_cast<const uint4*>(A  + (size_t)(row0 + r) * ASTR + lq * 8);
        rb[it] = *reinterpret_cast<const uint4*>(Bw + (size_t)(col0 + r) * ASTR + lq * 8);
    }

    for (int chunk = 0; chunk < TOTAL; chunk++) {
        const int buf   = chunk & 1;
        const uint32_t sbA = sb + (buf ? 2 * TBYTES : 0);
        const uint32_t sbB = sbA + TBYTES;

        // staged regs -> swizzled smem
#pragma unroll
        for (int it = 0; it < 4; it++) {
            const int r = lr + it * 32;
            const int sw = ((lq ^ (r & 7)) * 16);
            *reinterpret_cast<uint4*>(smem_raw + (sbA - sb) + r * 128 + sw) = ra[it];
            *reinterpret_cast<uint4*>(smem_raw + (sbB - sb) + r * 128 + sw) = rb[it];
        }
        __syncthreads();

        // prefetch next chunk
        if (chunk + 1 < TOTAL) {
            const int nxt  = chunk + 1;
            const int nseg = nxt / CPS;
            const int k0   = (nxt % CPS) * BK;
            const int aoff = (nseg == 1) ? KSEG : 0;   // pass 1: A-lo * B-hi
            const int boff = (nseg == 2) ? KSEG : 0;   // pass 2: A-hi * B-lo
#pragma unroll
            for (int it = 0; it < 4; it++) {
                const int r = lr + it * 32;
                ra[it] = *reinterpret_cast<const uint4*>(
                    A  + (size_t)(row0 + r) * ASTR + aoff + k0 + lq * 8);
                rb[it] = *reinterpret_cast<const uint4*>(
                    Bw + (size_t)(col0 + r) * ASTR + boff + k0 + lq * 8);
            }
        }

        // compute: 4 k16 steps on current buffer
#pragma unroll
        for (int step = 0; step < 4; step++) {
            const int kb8 = step * 2;      // 8-elem chunk index of k-lo half

            uint32_t af[2][4];
#pragma unroll
            for (int i = 0; i < 2; i++) {
                const int rowA = wm * 32 + i * 16 + r8 + (sub & 1) * 8;
                const int kc   = kb8 + (sub >> 1);
                ldsm_x4(af[i], sbA + rowA * 128 + ((kc ^ (rowA & 7)) * 16));
            }
            uint32_t bfr[8][2];
#pragma unroll
            for (int jj = 0; jj < 4; jj++) {
                const int rowB = wn * 64 + jj * 16 + r8 + (sub >> 1) * 8;
                const int kc   = kb8 + (sub & 1);
                uint32_t q[4];
                ldsm_x4(q, sbB + rowB * 128 + ((kc ^ (rowB & 7)) * 16));
                bfr[jj * 2][0]     = q[0]; bfr[jj * 2][1]     = q[1];
                bfr[jj * 2 + 1][0] = q[2]; bfr[jj * 2 + 1][1] = q[3];
            }
#pragma unroll
            for (int i = 0; i < 2; i++)
#pragma unroll
                for (int j = 0; j < 8; j++)
                    mma16816(acc[i][j], af[i], bfr[j]);
        }
        __syncthreads();
    }

    // ---- epilogue: fragment -> global, fused bias + ReLU ----
    const int g  = lane >> 2;              // row within 8
    const int qp = (lane & 3) * 2;         // col pair within n8

#pragma unroll
    for (int i = 0; i < 2; i++) {
        const int mlo = row0 + wm * 32 + i * 16 + g;
        const int mhi = mlo + 8;
#pragma unroll
        for (int j = 0; j < 8; j++) {
            const int col = col0 + wn * 64 + j * 8 + qp;
            const float bv0 = bias[col], bv1 = bias[col + 1];
            const float v00 = fmaxf(acc[i][j][0] + bv0, 0.0f);
            const float v01 = fmaxf(acc[i][j][1] + bv1, 0.0f);
            const float v10 = fmaxf(acc[i][j][2] + bv0, 0.0f);
            const float v11 = fmaxf(acc[i][j][3] + bv1, 0.0f);

            if (OUT_SPLIT) {
                __nv_bfloat16* rlo = reinterpret_cast<__nv_bfloat16*>(Cout) + (size_t)mlo * 2 * NT;
                __nv_bfloat16* rhi = reinterpret_cast<__nv_bfloat16*>(Cout) + (size_t)mhi * 2 * NT;
                __nv_bfloat16 h0, l0, h1, l1;
                split_bf16(v00, h0, l0); split_bf16(v01, h1, l1);
                __nv_bfloat162 hh; hh.x = h0; hh.y = h1;
                __nv_bfloat162 ll; ll.x = l0; ll.y = l1;
                *reinterpret_cast<__nv_bfloat162*>(rlo + col)      = hh;
                *reinterpret_cast<__nv_bfloat162*>(rlo + NT + col) = ll;
                split_bf16(v10, h0, l0); split_bf16(v11, h1, l1);
                hh.x = h0; hh.y = h1; ll.x = l0; ll.y = l1;
                *reinterpret_cast<__nv_bfloat162*>(rhi + col)      = hh;
                *reinterpret_cast<__nv_bfloat162*>(rhi + NT + col) = ll;
            } else {
                float* Cf = reinterpret_cast<float*>(Cout);
                float2 plo; plo.x = v00; plo.y = v01;
                float2 phi; phi.x = v10; phi.y = v11;
                *reinterpret_cast<float2*>(Cf + (size_t)mlo * NT + col) = plo;
                *reinterpret_cast<float2*>(Cf + (size_t)mhi * NT + col) = phi;
            }
        }
    }
}

// ---------------------------------------------------------------------------
// final GEMV: out[b] = dot(h2[b,:], W3) + b3 (one warp per row)
// ---------------------------------------------------------------------------
__global__ void gemv3_kernel(const float* __restrict__ W3,
                             const float* __restrict__ b3,
                             float*       __restrict__ out)
{
    const int gwarp = (blockIdx.x * blockDim.x + threadIdx.x) >> 5;
    const int lane  = threadIdx.x & 31;
    if (gwarp >= B_) return;
    const float* r = g_h2 + (size_t)gwarp * H2_;
    float acc = 0.0f;
#pragma unroll
    for (int k = lane; k < H2_; k += 32) acc = fmaf(r[k], W3[k], acc);
#pragma unroll
    for (int o = 16; o; o >>= 1) acc += __shfl_xor_sync(0xFFFFFFFFu, acc, o);
    if (lane == 0) out[gwarp] = acc + b3[0];
}

// ---------------------------------------------------------------------------
// launch
// ---------------------------------------------------------------------------
extern "C" void kernel_launch(void* const* d_in, const int* in_sizes, int n_in,
                              void* d_out, int out_size)
{
    const int*   idx    = (const int*)  d_in[0];
    const float* tables = (const float*)d_in[1];
    const float* W1     = (const float*)d_in[2];
    const float* b1     = (const float*)d_in[3];
    const float* W2     = (const float*)d_in[4];
    const float* b2     = (const float*)d_in[5];
    const float* W3     = (const float*)d_in[6];
    const float* b3     = (const float*)d_in[7];
    float*       out    = (float*)d_out;

    __nv_bfloat16 *A, *W1t, *W2t, *h1b; float* h2;
    cudaGetSymbolAddress((void**)&A,   g_A);
    cudaGetSymbolAddress((void**)&W1t, g_W1t);
    cudaGetSymbolAddress((void**)&W2t, g_W2t);
    cudaGetSymbolAddress((void**)&h1b, g_h1b);
    cudaGetSymbolAddress((void**)&h2,  g_h2);

    const int SMEM = 4 * 128 * 128;   // 64 KB: A0|B0|A1|B1
    cudaFuncSetAttribute(gemm_mma_kernel<512, 2048, true>,
                         cudaFuncAttributeMaxDynamicSharedMemorySize, SMEM);
    cudaFuncSetAttribute(gemm_mma_kernel<256, 512, false>,
                         cudaFuncAttributeMaxDynamicSharedMemorySize, SMEM);

    prep_w1_kernel<<<(H1_ * K1 + 255) / 256, 256>>>(W1);
    prep_w2_kernel<<<(H2_ * K2 + 255) / 256, 256>>>(W2);
    build_joint_kernel<<<B_, 128>>>(idx, tables);

    // layer 1: [B,2048] x [2048,512] (split bf16, 3 passes) -> h1 split bf16
    {
        dim3 grid(H1_ / 128, B_ / 128);
        gemm_mma_kernel<512, 2048, true><<<grid, 256, SMEM>>>(A, W1t, b1, h1b);
    }
    // layer 2: [B,512] x [512,256] -> h2 fp32
    {
        dim3 grid(H2_ / 128, B_ / 128);
        gemm_mma_kernel<256, 512, false><<<grid, 256, SMEM>>>(h1b, W2t, b2, h2);
    }
    // layer 3
    gemv3_kernel<<<(B_ * 32 + 255) / 256, 256>>>(W3, b3, out);
}